// round 16
// baseline (speedup 1.0000x reference)
#include <cuda_runtime.h>
#include <cuda_fp16.h>
#include <math.h>

#define BB 2
#define NN 4096
#define DIMD 1024
#define HEADS 16
#define DH 64
#define WW 512
#define NW (NN/WW)          // 8
#define INNER 2730
#define GGW2 2752           // = FF1NP/2, padded GEGLU output width
#define ROWS (BB*NN)        // 8192
#define QKVN (3*HEADS*DH)   // 3072
#define FF1N (2*INNER)      // 5460
#define FF1NP 5504          // padded/permuted FF1 N (43*128)

typedef __half h16;

// ------------------- scratch (device globals; no allocation) -------------------
__device__ h16   g_hh  [ROWS*DIMD];
__device__ h16   g_qh  [BB*HEADS*NN*DH];
__device__ h16   g_kh  [BB*HEADS*NN*DH];
__device__ h16   g_vh  [BB*HEADS*NN*DH];
__device__ h16   g_attnh[ROWS*DIMD];
__device__ float g_x1  [ROWS*DIMD];
__device__ h16   g_ggh [ROWS*GGW2];
__device__ float2 g_cs [NN*32];        // rotary cos/sin table
__device__ h16   g_wqkv[DIMD*QKVN];    // q/k sections column-permuted (rope pairs adjacent)
__device__ h16   g_wout[DIMD*DIMD];
__device__ h16   g_wff1[DIMD*FF1NP];   // interleaved: col 2c = a_c, 2c+1 = g_c
__device__ h16   g_wff2[INNER*DIMD];

__device__ __forceinline__ unsigned cvta_s(const void* p) {
    return (unsigned)__cvta_generic_to_shared(p);
}
__device__ __forceinline__ float ex2f(float x) {
    float y; asm("ex2.approx.ftz.f32 %0, %1;" : "=f"(y) : "f"(x)); return y;
}
__device__ __forceinline__ void mma16816(float* c, const unsigned* a, unsigned b0, unsigned b1) {
    asm volatile(
        "mma.sync.aligned.m16n8k16.row.col.f32.f16.f16.f32 "
        "{%0,%1,%2,%3}, {%4,%5,%6,%7}, {%8,%9}, {%0,%1,%2,%3};\n"
        : "+f"(c[0]), "+f"(c[1]), "+f"(c[2]), "+f"(c[3])
        : "r"(a[0]), "r"(a[1]), "r"(a[2]), "r"(a[3]), "r"(b0), "r"(b1));
}
__device__ __forceinline__ void ldsm4(unsigned* r, unsigned addr) {
    asm volatile("ldmatrix.sync.aligned.m8n8.x4.shared.b16 {%0,%1,%2,%3}, [%4];\n"
                 : "=r"(r[0]), "=r"(r[1]), "=r"(r[2]), "=r"(r[3]) : "r"(addr));
}
__device__ __forceinline__ void ldsm4t(unsigned* r, unsigned addr) {
    asm volatile("ldmatrix.sync.aligned.m8n8.x4.trans.shared.b16 {%0,%1,%2,%3}, [%4];\n"
                 : "=r"(r[0]), "=r"(r[1]), "=r"(r[2]), "=r"(r[3]) : "r"(addr));
}
__device__ __forceinline__ unsigned packh2(float a, float b) {
    half2 h = __floats2half2_rn(a, b);
    return *(unsigned*)&h;
}

#define QSCALE (0.125f * 1.44269504088896341f)

// ------------------- merged pre-processing (tables + weight converts) -------------------
#define CS_N    (NN*32)
#define QKV_N   (DIMD*(QKVN/2))
#define WOUT_N  (DIMD*DIMD/4)
#define WFF2_N  (INNER*DIMD/4)
#define FF1_N   (DIMD*(FF1NP/2))
#define CS_B    ((CS_N+255)/256)
#define QKV_B   (CS_B + (QKV_N+255)/256)
#define WOUT_B  (QKV_B + (WOUT_N+255)/256)
#define WFF2_B  (WOUT_B + (WFF2_N+255)/256)
#define FF1_B   (WFF2_B + (FF1_N+255)/256)

__global__ __launch_bounds__(256) void prep_kernel(
    const float* __restrict__ w_qkv, const float* __restrict__ w_out,
    const float* __restrict__ w_ff2, const float* __restrict__ w_ff1,
    float2* __restrict__ T, h16* __restrict__ dqkv, h16* __restrict__ dout,
    h16* __restrict__ dff2, h16* __restrict__ dff1)
{
    int blk = blockIdx.x;
    if (blk < CS_B) {
        int idx = blk * 256 + threadIdx.x;
        if (idx >= CS_N) return;
        int n = idx >> 5, dj = idx & 31;
        float inv = powf(10000.f, -(float)dj * (1.f / 32.f));
        float f = (float)n * inv;
        float sn, cs; sincosf(f, &sn, &cs);
        T[idx] = make_float2(cs, sn);
    } else if (blk < QKV_B) {
        int idx = (blk - CS_B) * 256 + threadIdx.x;
        if (idx >= QKV_N) return;
        int row = idx / (QKVN / 2);
        int p = idx - row * (QKVN / 2);
        int col = p * 2;
        int sect = col >> 10, c = col & 1023;
        const float* rbase = w_qkv + (size_t)row * QKVN;
        float v0, v1;
        if (sect < 2) {
            int h = c >> 6, dj = (c & 63) >> 1;
            v0 = rbase[sect * 1024 + h * 64 + dj];
            v1 = rbase[sect * 1024 + h * 64 + dj + 32];
        } else {
            float2 vv = *(const float2*)(rbase + col);
            v0 = vv.x; v1 = vv.y;
        }
        ((half2*)dqkv)[idx] = __floats2half2_rn(v0, v1);
    } else if (blk < WOUT_B) {
        int i = (blk - QKV_B) * 256 + threadIdx.x;
        if (i >= WOUT_N) return;
        float4 v = ((const float4*)w_out)[i];
        half2* d = (half2*)dout + i * 2;
        d[0] = __floats2half2_rn(v.x, v.y);
        d[1] = __floats2half2_rn(v.z, v.w);
    } else if (blk < WFF2_B) {
        int i = (blk - WOUT_B) * 256 + threadIdx.x;
        if (i >= WFF2_N) return;
        float4 v = ((const float4*)w_ff2)[i];
        half2* d = (half2*)dff2 + i * 2;
        d[0] = __floats2half2_rn(v.x, v.y);
        d[1] = __floats2half2_rn(v.z, v.w);
    } else {
        int idx = (blk - WFF2_B) * 256 + threadIdx.x;
        if (idx >= FF1_N) return;
        int row = idx / (FF1NP / 2);
        int c = idx - row * (FF1NP / 2);
        float a = 0.f, g = 0.f;
        if (c < INNER) {
            const float* rbase = w_ff1 + (size_t)row * FF1N;
            a = rbase[c];
            g = rbase[INNER + c];
        }
        ((half2*)dff1)[(size_t)row * (FF1NP / 2) + c] = __floats2half2_rn(a, g);
    }
}

// ------------------------------- LayerNorm -------------------------------
__global__ __launch_bounds__(256) void ln_kernel(
    const float* __restrict__ X, const float* __restrict__ w,
    const float* __restrict__ b, h16* __restrict__ Y)
{
    __shared__ float sa[8], sb[8];
    int row = blockIdx.x;
    int t = threadIdx.x;
    const float4* xr = (const float4*)(X + (size_t)row * DIMD);
    float4 xv = xr[t];
    float s  = xv.x + xv.y + xv.z + xv.w;
    float sq = xv.x*xv.x + xv.y*xv.y + xv.z*xv.z + xv.w*xv.w;

    int lane = t & 31, wrp = t >> 5;
    #pragma unroll
    for (int o = 16; o; o >>= 1) {
        s  += __shfl_xor_sync(0xffffffffu, s,  o);
        sq += __shfl_xor_sync(0xffffffffu, sq, o);
    }
    if (lane == 0) { sa[wrp] = s; sb[wrp] = sq; }
    __syncthreads();
    if (wrp == 0) {
        s  = (lane < 8) ? sa[lane] : 0.f;
        sq = (lane < 8) ? sb[lane] : 0.f;
        #pragma unroll
        for (int o = 4; o; o >>= 1) {
            s  += __shfl_xor_sync(0xffffffffu, s,  o);
            sq += __shfl_xor_sync(0xffffffffu, sq, o);
        }
        if (lane == 0) { sa[0] = s; sb[0] = sq; }
    }
    __syncthreads();
    float mean = sa[0] * (1.f / DIMD);
    float var  = sb[0] * (1.f / DIMD) - mean * mean;
    float inv  = rsqrtf(var + 1e-5f);

    float4 wv = ((const float4*)w)[t];
    float4 out;
    out.x = (xv.x - mean) * inv * wv.x;
    out.y = (xv.y - mean) * inv * wv.y;
    out.z = (xv.z - mean) * inv * wv.z;
    out.w = (xv.w - mean) * inv * wv.w;
    if (b) {
        float4 bv = ((const float4*)b)[t];
        out.x += bv.x; out.y += bv.y; out.z += bv.z; out.w += bv.w;
    }
    half2* yr = (half2*)(Y + (size_t)row * DIMD);
    yr[2 * t + 0] = __floats2half2_rn(out.x, out.y);
    yr[2 * t + 1] = __floats2half2_rn(out.z, out.w);
}

// --------------------------- tensor-core windowed attention (64q / 4 warps, 2-buf) ---------------------------
// __launch_bounds__(128, 5): cap regs ~102 -> 5 CTAs/SM (occupancy probe)
#define AT_STR 72
__global__ __launch_bounds__(128, 5) void attn_mma_kernel(
    const h16* __restrict__ Q, const h16* __restrict__ K,
    const h16* __restrict__ V, h16* __restrict__ O)
{
    __shared__ h16 Qs[64 * AT_STR];
    __shared__ h16 Ks[2][64 * AT_STR];
    __shared__ h16 Vs[2][64 * AT_STR];

    int idx = blockIdx.x;
    int qb = idx & 7;
    int wi = (idx >> 3) & 7;
    int h  = (idx >> 6) & 15;
    int b  = idx >> 10;
    int t  = threadIdx.x;
    int warp = t >> 5, lane = t & 31;
    int g = lane >> 2, q = lane & 3;

    const size_t bh = ((size_t)b * HEADS + h) * NN;
    int n0 = wi * WW + qb * 64;
    int tstart = (wi == 0) ? 8 : 0;
    int tend = qb + 8;

    #pragma unroll
    for (int i = 0; i < 4; i++) {
        int c = t + i * 128;
        int row = c >> 3, cc = c & 7;
        unsigned dst = cvta_s(Qs + row * AT_STR + cc * 8);
        const h16* src = Q + (bh + n0 + row) * DH + cc * 8;
        asm volatile("cp.async.cg.shared.global [%0], [%1], 16;\n" :: "r"(dst), "l"(src));
    }

    #define KV_ISSUE(tt_, buf_)                                                  \
    {                                                                            \
        int kg = wi * WW - WW + (tt_) * 64;                                      \
        _Pragma("unroll")                                                        \
        for (int i = 0; i < 4; i++) {                                            \
            int c = t + i * 128;                                                 \
            int row = c >> 3, cc = c & 7;                                        \
            const h16* ks_ = K + (bh + kg + row) * DH + cc * 8;                  \
            const h16* vs_ = V + (bh + kg + row) * DH + cc * 8;                  \
            unsigned kd = cvta_s(&Ks[buf_][row * AT_STR + cc * 8]);              \
            unsigned vd = cvta_s(&Vs[buf_][row * AT_STR + cc * 8]);              \
            asm volatile("cp.async.cg.shared.global [%0], [%1], 16;\n" :: "r"(kd), "l"(ks_)); \
            asm volatile("cp.async.cg.shared.global [%0], [%1], 16;\n" :: "r"(vd), "l"(vs_)); \
        }                                                                        \
    }

    KV_ISSUE(tstart, 0);
    asm volatile("cp.async.commit_group;\n" ::: "memory");
    if (tstart < tend) { KV_ISSUE(tstart + 1, 1); }
    asm volatile("cp.async.commit_group;\n" ::: "memory");

    float o_[8][4];
    #pragma unroll
    for (int i = 0; i < 8; i++)
        #pragma unroll
        for (int j = 0; j < 4; j++) o_[i][j] = 0.f;
    float m0 = -1e30f, m1 = -1e30f, l0 = 0.f, l1 = 0.f;

    int bsel = 0;
    for (int tt = tstart; tt <= tend; tt++) {
        asm volatile("cp.async.wait_group 1;\n" ::: "memory");
        __syncthreads();

        float sc[8][4];
        #pragma unroll
        for (int i = 0; i < 8; i++)
            #pragma unroll
            for (int j = 0; j < 4; j++) sc[i][j] = 0.f;

        #pragma unroll
        for (int ks = 0; ks < 4; ks++) {
            unsigned aq[4];
            ldsm4(aq, cvta_s(Qs + (warp * 16 + (lane & 15)) * AT_STR
                             + ks * 16 + ((lane >> 4) << 3)));
            #pragma unroll
            for (int nb = 0; nb < 4; nb++) {
                unsigned bk[4];
                int krow = nb * 16 + (lane & 7) + ((lane >> 4) << 3);
                int kcol = ks * 16 + (((lane >> 3) & 1) << 3);
                ldsm4(bk, cvta_s(&Ks[bsel][krow * AT_STR + kcol]));
                mma16816(sc[nb * 2],     aq, bk[0], bk[1]);
                mma16816(sc[nb * 2 + 1], aq, bk[2], bk[3]);
            }
        }

        if (tt == tend) {
            int r0 = warp * 16 + g, r1 = r0 + 8;
            #pragma unroll
            for (int nf = 0; nf < 8; nf++) {
                int c0 = nf * 8 + q * 2;
                if (c0     > r0) sc[nf][0] = -1e30f;
                if (c0 + 1 > r0) sc[nf][1] = -1e30f;
                if (c0     > r1) sc[nf][2] = -1e30f;
                if (c0 + 1 > r1) sc[nf][3] = -1e30f;
            }
        }

        float mt0 = -1e30f, mt1 = -1e30f;
        #pragma unroll
        for (int nf = 0; nf < 8; nf++) {
            mt0 = fmaxf(mt0, fmaxf(sc[nf][0], sc[nf][1]));
            mt1 = fmaxf(mt1, fmaxf(sc[nf][2], sc[nf][3]));
        }
        mt0 = fmaxf(mt0, __shfl_xor_sync(0xffffffffu, mt0, 1));
        mt0 = fmaxf(mt0, __shfl_xor_sync(0xffffffffu, mt0, 2));
        mt1 = fmaxf(mt1, __shfl_xor_sync(0xffffffffu, mt1, 1));
        mt1 = fmaxf(mt1, __shfl_xor_sync(0xffffffffu, mt1, 2));
        float mn0 = fmaxf(m0, mt0), mn1 = fmaxf(m1, mt1);
        float cor0 = ex2f(m0 - mn0), cor1 = ex2f(m1 - mn1);
        m0 = mn0; m1 = mn1;
        float s0 = 0.f, s1 = 0.f;
        #pragma unroll
        for (int nf = 0; nf < 8; nf++) {
            sc[nf][0] = ex2f(sc[nf][0] - mn0);
            sc[nf][1] = ex2f(sc[nf][1] - mn0);
            sc[nf][2] = ex2f(sc[nf][2] - mn1);
            sc[nf][3] = ex2f(sc[nf][3] - mn1);
            s0 += sc[nf][0] + sc[nf][1];
            s1 += sc[nf][2] + sc[nf][3];
        }
        l0 = l0 * cor0 + s0;
        l1 = l1 * cor1 + s1;
        #pragma unroll
        for (int nf = 0; nf < 8; nf++) {
            o_[nf][0] *= cor0; o_[nf][1] *= cor0;
            o_[nf][2] *= cor1; o_[nf][3] *= cor1;
        }

        #pragma unroll
        for (int ks = 0; ks < 4; ks++) {
            unsigned ap[4];
            ap[0] = packh2(sc[2 * ks][0],     sc[2 * ks][1]);
            ap[1] = packh2(sc[2 * ks][2],     sc[2 * ks][3]);
            ap[2] = packh2(sc[2 * ks + 1][0], sc[2 * ks + 1][1]);
            ap[3] = packh2(sc[2 * ks + 1][2], sc[2 * ks + 1][3]);
            #pragma unroll
            for (int nb = 0; nb < 4; nb++) {
                unsigned bv[4];
                ldsm4t(bv, cvta_s(&Vs[bsel][(ks * 16 + (lane & 15)) * AT_STR
                                            + nb * 16 + ((lane >> 4) << 3)]));
                mma16816(o_[nb * 2],     ap, bv[0], bv[1]);
                mma16816(o_[nb * 2 + 1], ap, bv[2], bv[3]);
            }
        }

        __syncthreads();
        if (tt + 2 <= tend) { KV_ISSUE(tt + 2, bsel); }
        asm volatile("cp.async.commit_group;\n" ::: "memory");
        bsel ^= 1;
    }

    l0 += __shfl_xor_sync(0xffffffffu, l0, 1);
    l0 += __shfl_xor_sync(0xffffffffu, l0, 2);
    l1 += __shfl_xor_sync(0xffffffffu, l1, 1);
    l1 += __shfl_xor_sync(0xffffffffu, l1, 2);
    float li0 = 1.f / l0, li1 = 1.f / l1;

    int row0 = n0 + warp * 16 + g;
    h16* p0 = O + ((size_t)(b * NN + row0)) * DIMD + h * DH;
    h16* p1 = O + ((size_t)(b * NN + row0 + 8)) * DIMD + h * DH;
    #pragma unroll
    for (int nf = 0; nf < 8; nf++) {
        *(half2*)(p0 + nf * 8 + q * 2) = __floats2half2_rn(o_[nf][0] * li0, o_[nf][1] * li0);
        *(half2*)(p1 + nf * 8 + q * 2) = __floats2half2_rn(o_[nf][2] * li1, o_[nf][3] * li1);
    }
    #undef KV_ISSUE
}

// ------------------------------ FP16 tensor-core GEMM (128x128, k64 x 3-stage) ------------------------------
// OUTMODE: 0 = fp32 out, 1 = fp16 out, 2 = fused GEGLU,
//          3 = fused rope + q/k/v head split
#define STAGES 3
#define ASTR 72
#define BSTR 136
#define A_STAGE (128*ASTR)
#define B_STAGE (64*BSTR)
#define GEMM_SMEM (STAGES*(A_STAGE+B_STAGE)*2)

template<bool RES, int OUTMODE>
__global__ __launch_bounds__(256) void h16_gemm(
    const h16* __restrict__ A, int lda,
    const h16* __restrict__ B, int ldb,
    const float* __restrict__ R, void* __restrict__ Cv,
    int Nc, int Kb, int Kpad,
    const float2* __restrict__ CS = nullptr,
    h16* __restrict__ Qo = nullptr, h16* __restrict__ Ko = nullptr,
    h16* __restrict__ Vo = nullptr)
{
    extern __shared__ char smem_raw[];
    h16* As = (h16*)smem_raw;
    h16* Bs = (h16*)(smem_raw + (size_t)STAGES * A_STAGE * 2);

    const int t = threadIdx.x;
    const int rowBase = blockIdx.y * 128, colBase = blockIdx.x * 128;
    const int warp = t >> 5, lane = t & 31;
    const int wm = warp >> 2, wn = warp & 3;
    const int q = lane & 3, g = lane >> 2;

    float acc[4][4][4];
    #pragma unroll
    for (int i = 0; i < 4; i++)
        #pragma unroll
        for (int j = 0; j < 4; j++)
            #pragma unroll
            for (int rr = 0; rr < 4; rr++) acc[i][j][rr] = 0.f;

    #define ISSUE(k0, s)                                                        \
    {                                                                           \
        _Pragma("unroll")                                                       \
        for (int i = 0; i < 4; i++) {                                           \
            int c = t + i * 256;                                                \
            int row = c >> 3, cc = c & 7;                                       \
            const h16* src = A + (size_t)(rowBase + row) * lda + (k0) + cc * 8; \
            unsigned dst = cvta_s(As + (s) * A_STAGE + row * ASTR + cc * 8);    \
            asm volatile("cp.async.cg.shared.global [%0], [%1], 16;\n"          \
                         :: "r"(dst), "l"(src));                                \
        }                                                                       \
        _Pragma("unroll")                                                       \
        for (int i = 0; i < 4; i++) {                                           \
            int c = t + i * 256;                                                \
            int row = c >> 4, cc = c & 15;                                      \
            int kidx = (k0) + row;                                              \
            int bytes = (kidx < Kb) ? 16 : 0;                                   \
            const h16* src = B + (size_t)(kidx < Kb ? kidx : 0) * ldb           \
                               + colBase + cc * 8;                              \
            unsigned dst = cvta_s(Bs + (s) * B_STAGE + row * BSTR + cc * 8);    \
            asm volatile("cp.async.cg.shared.global [%0], [%1], 16, %2;\n"      \
                         :: "r"(dst), "l"(src), "r"(bytes));                    \
        }                                                                       \
    }

    #define COMPUTE(s)                                                          \
    {                                                                           \
        _Pragma("unroll")                                                       \
        for (int ks = 0; ks < 64; ks += 16) {                                   \
            unsigned a[4][4], bfr[2][4];                                        \
            _Pragma("unroll")                                                   \
            for (int mf = 0; mf < 4; mf++) {                                    \
                int mrow = wm * 64 + mf * 16 + (lane & 15);                     \
                int colofs = ks + ((lane >> 4) << 3);                           \
                ldsm4(a[mf], cvta_s(As + (s) * A_STAGE + mrow * ASTR + colofs));\
            }                                                                   \
            _Pragma("unroll")                                                   \
            for (int nh = 0; nh < 2; nh++) {                                    \
                int krow = ks + (lane & 15);                                    \
                int col = wn * 32 + nh * 16 + ((lane >> 4) << 3);               \
                ldsm4t(bfr[nh], cvta_s(Bs + (s) * B_STAGE + krow * BSTR + col));\
            }                                                                   \
            _Pragma("unroll")                                                   \
            for (int mf = 0; mf < 4; mf++)                                      \
                _Pragma("unroll")                                               \
                for (int nf = 0; nf < 4; nf++)                                  \
                    mma16816(acc[mf][nf], a[mf],                                \
                             bfr[nf >> 1][(nf & 1) * 2 + 0],                    \
                             bfr[nf >> 1][(nf & 1) * 2 + 1]);                   \
        }                                                                       \
    }

    const int nstage = Kpad / 64;
    ISSUE(0, 0);
    asm volatile("cp.async.commit_group;\n" ::: "memory");
    ISSUE(64, 1);
    asm volatile("cp.async.commit_group;\n" ::: "memory");

    for (int it = 0; it < nstage; it++) {
        asm volatile("cp.async.wait_group 1;\n" ::: "memory");
        __syncthreads();
        int s = it % 3;
        COMPUTE(s);
        if (it + 2 < nstage) {
            int k0 = (it + 2) * 64;
            int s2 = (it + 2) % 3;
            ISSUE(k0, s2);
        }
        asm volatile("cp.async.commit_group;\n" ::: "memory");
    }

    #pragma unroll
    for (int mf = 0; mf < 4; mf++) {
        #pragma unroll
        for (int i = 0; i < 2; i++) {
            int grow = rowBase + wm * 64 + mf * 16 + g + i * 8;
            #pragma unroll
            for (int nf = 0; nf < 4; nf++) {
                int gcol = colBase + wn * 32 + nf * 8 + q * 2;
                if (gcol < Nc) {
                    float v0 = acc[mf][nf][i * 2 + 0];
                    float v1 = acc[mf][nf][i * 2 + 1];
                    if (RES) {
                        const float* Rp = R + (size_t)grow * Nc + gcol;
                        v0 += Rp[0]; v1 += Rp[1];
                    }
                    if (OUTMODE == 0) {
                        float* Cf = (float*)Cv;
                        *(float2*)(Cf + (size_t)grow * Nc + gcol) = make_float2(v0, v1);
                    } else if (OUTMODE == 1) {
                        h16* Ch = (h16*)Cv;
                        *(half2*)(Ch + (size_t)grow * Nc + gcol) = __floats2half2_rn(v0, v1);
                    } else if (OUTMODE == 2) {
                        float ge = 0.5f * v1 * (1.f + erff(v1 * 0.70710678118654752f));
                        h16* Ch = (h16*)Cv;
                        Ch[(size_t)grow * (Nc / 2) + (gcol >> 1)] = __float2half_rn(v0 * ge);
                    } else {
                        int sect = gcol >> 10, c = gcol & 1023;
                        int hh = c >> 6, r = c & 63;
                        int bb2 = grow >> 12, n = grow & (NN - 1);
                        size_t o = ((size_t)(bb2 * HEADS + hh) * NN + n) * DH + r;
                        if (sect == 2) {
                            *(half2*)(Vo + o) = __floats2half2_rn(v0, v1);
                        } else {
                            int dj = r >> 1;
                            float2 cs = CS[n * 32 + dj];
                            float y0 = v0 * cs.x - v1 * cs.y;
                            float y1 = v1 * cs.x + v0 * cs.y;
                            if (sect == 0) { y0 *= QSCALE; y1 *= QSCALE; }
                            h16* P = (sect == 0) ? Qo : Ko;
                            *(half2*)(P + o) = __floats2half2_rn(y0, y1);
                        }
                    }
                }
            }
        }
    }
    #undef ISSUE
    #undef COMPUTE
}

// ------------------------------ launch ------------------------------
extern "C" void kernel_launch(void* const* d_in, const int* in_sizes, int n_in,
                              void* d_out, int out_size)
{
    const float* x     = (const float*)d_in[0];
    const float* ln1_w = (const float*)d_in[1];
    const float* ln1_b = (const float*)d_in[2];
    const float* w_qkv = (const float*)d_in[3];
    const float* w_out = (const float*)d_in[4];
    const float* ln2_w = (const float*)d_in[5];
    const float* w_ff1 = (const float*)d_in[6];
    const float* w_ff2 = (const float*)d_in[7];
    float* out = (float*)d_out;

    h16 *p_hh, *p_qh, *p_kh, *p_vh, *p_attnh, *p_ggh;
    h16 *p_wqkv, *p_wout, *p_wff1, *p_wff2;
    float *p_x1;
    float2 *p_cs;
    cudaGetSymbolAddress((void**)&p_hh,    g_hh);
    cudaGetSymbolAddress((void**)&p_qh,    g_qh);
    cudaGetSymbolAddress((void**)&p_kh,    g_kh);
    cudaGetSymbolAddress((void**)&p_vh,    g_vh);
    cudaGetSymbolAddress((void**)&p_attnh, g_attnh);
    cudaGetSymbolAddress((void**)&p_x1,    g_x1);
    cudaGetSymbolAddress((void**)&p_ggh,   g_ggh);
    cudaGetSymbolAddress((void**)&p_cs,    g_cs);
    cudaGetSymbolAddress((void**)&p_wqkv,  g_wqkv);
    cudaGetSymbolAddress((void**)&p_wout,  g_wout);
    cudaGetSymbolAddress((void**)&p_wff1,  g_wff1);
    cudaGetSymbolAddress((void**)&p_wff2,  g_wff2);

    cudaFuncSetAttribute(h16_gemm<false,2>, cudaFuncAttributeMaxDynamicSharedMemorySize, GEMM_SMEM);
    cudaFuncSetAttribute(h16_gemm<false,3>, cudaFuncAttributeMaxDynamicSharedMemorySize, GEMM_SMEM);
    cudaFuncSetAttribute(h16_gemm<true,0>,  cudaFuncAttributeMaxDynamicSharedMemorySize, GEMM_SMEM);

    // 0. merged tables + weight converts
    prep_kernel<<<FF1_B, 256>>>(w_qkv, w_out, w_ff2, w_ff1,
                                p_cs, p_wqkv, p_wout, p_wff2, p_wff1);

    // 1. LN1 -> fp16
    ln_kernel<<<ROWS, 256>>>(x, ln1_w, ln1_b, p_hh);
    // 2. QKV GEMM + fused rope + head split (M=8192, N=3072, K=1024)
    h16_gemm<false,3><<<dim3(QKVN / 128, ROWS / 128), 256, GEMM_SMEM>>>(
        p_hh, DIMD, p_wqkv, QKVN, nullptr, nullptr, QKVN, DIMD, DIMD,
        p_cs, p_qh, p_kh, p_vh);
    // 3. tensor-core windowed attention (64q / 4 warps, occupancy-capped regs)
    attn_mma_kernel<<<BB * HEADS * NW * (WW / 64), 128>>>(p_qh, p_kh, p_vh, p_attnh);
    // 4. out proj + residual (M=8192, N=1024, K=1024) -> fp32
    h16_gemm<true,0><<<dim3(DIMD / 128, ROWS / 128), 256, GEMM_SMEM>>>(
        p_attnh, DIMD, p_wout, DIMD, x, p_x1, DIMD, DIMD, DIMD);
    // 5. LN2 -> fp16
    ln_kernel<<<ROWS, 256>>>(p_x1, ln2_w, nullptr, p_hh);
    // 6. FF1 + fused GEGLU (M=8192, Nc=5504 interleaved, K=1024) -> gg fp16 [8192 x 2752]
    h16_gemm<false,2><<<dim3(FF1NP / 128, ROWS / 128), 256, GEMM_SMEM>>>(
        p_hh, DIMD, p_wff1, FF1NP, nullptr, p_ggh, FF1NP, DIMD, DIMD);
    // 7. FF2 + residual -> out (M=8192, N=1024, K=2752 incl. exact zero pad)
    h16_gemm<true,0><<<dim3(DIMD / 128, ROWS / 128), 256, GEMM_SMEM>>>(
        p_ggh, GGW2, p_wff2, DIMD, p_x1, out, DIMD, INNER, GGW2);
}

// round 17
// speedup vs baseline: 1.0123x; 1.0123x over previous
#include <cuda_runtime.h>
#include <cuda_fp16.h>
#include <math.h>

#define BB 2
#define NN 4096
#define DIMD 1024
#define HEADS 16
#define DH 64
#define WW 512
#define NW (NN/WW)          // 8
#define INNER 2730
#define GGW2 2752           // = FF1NP/2, padded GEGLU output width
#define ROWS (BB*NN)        // 8192
#define QKVN (3*HEADS*DH)   // 3072
#define FF1N (2*INNER)      // 5460
#define FF1NP 5504          // padded/permuted FF1 N (43*128)

typedef __half h16;

// ------------------- scratch (device globals; no allocation) -------------------
__device__ h16   g_hh  [ROWS*DIMD];
__device__ h16   g_qh  [BB*HEADS*NN*DH];
__device__ h16   g_kh  [BB*HEADS*NN*DH];
__device__ h16   g_vh  [BB*HEADS*NN*DH];
__device__ h16   g_attnh[ROWS*DIMD];
__device__ float g_x1  [ROWS*DIMD];
__device__ h16   g_ggh [ROWS*GGW2];
__device__ float2 g_cs [NN*32];        // rotary cos/sin table
__device__ h16   g_wqkv[DIMD*QKVN];    // q/k sections column-permuted (rope pairs adjacent)
__device__ h16   g_wout[DIMD*DIMD];
__device__ h16   g_wff1[DIMD*FF1NP];   // interleaved: col 2c = a_c, 2c+1 = g_c
__device__ h16   g_wff2[INNER*DIMD];

__device__ __forceinline__ unsigned cvta_s(const void* p) {
    return (unsigned)__cvta_generic_to_shared(p);
}
__device__ __forceinline__ float ex2f(float x) {
    float y; asm("ex2.approx.ftz.f32 %0, %1;" : "=f"(y) : "f"(x)); return y;
}
__device__ __forceinline__ void mma16816(float* c, const unsigned* a, unsigned b0, unsigned b1) {
    asm volatile(
        "mma.sync.aligned.m16n8k16.row.col.f32.f16.f16.f32 "
        "{%0,%1,%2,%3}, {%4,%5,%6,%7}, {%8,%9}, {%0,%1,%2,%3};\n"
        : "+f"(c[0]), "+f"(c[1]), "+f"(c[2]), "+f"(c[3])
        : "r"(a[0]), "r"(a[1]), "r"(a[2]), "r"(a[3]), "r"(b0), "r"(b1));
}
__device__ __forceinline__ void ldsm4(unsigned* r, unsigned addr) {
    asm volatile("ldmatrix.sync.aligned.m8n8.x4.shared.b16 {%0,%1,%2,%3}, [%4];\n"
                 : "=r"(r[0]), "=r"(r[1]), "=r"(r[2]), "=r"(r[3]) : "r"(addr));
}
__device__ __forceinline__ void ldsm4t(unsigned* r, unsigned addr) {
    asm volatile("ldmatrix.sync.aligned.m8n8.x4.trans.shared.b16 {%0,%1,%2,%3}, [%4];\n"
                 : "=r"(r[0]), "=r"(r[1]), "=r"(r[2]), "=r"(r[3]) : "r"(addr));
}
__device__ __forceinline__ unsigned packh2(float a, float b) {
    half2 h = __floats2half2_rn(a, b);
    return *(unsigned*)&h;
}

#define QSCALE (0.125f * 1.44269504088896341f)

// ------------------- merged pre-processing (tables + weight converts) -------------------
#define CS_N    (NN*32)
#define QKV_N   (DIMD*(QKVN/2))
#define WOUT_N  (DIMD*DIMD/4)
#define WFF2_N  (INNER*DIMD/4)
#define FF1_N   (DIMD*(FF1NP/2))
#define CS_B    ((CS_N+255)/256)
#define QKV_B   (CS_B + (QKV_N+255)/256)
#define WOUT_B  (QKV_B + (WOUT_N+255)/256)
#define WFF2_B  (WOUT_B + (WFF2_N+255)/256)
#define FF1_B   (WFF2_B + (FF1_N+255)/256)

__global__ __launch_bounds__(256) void prep_kernel(
    const float* __restrict__ w_qkv, const float* __restrict__ w_out,
    const float* __restrict__ w_ff2, const float* __restrict__ w_ff1,
    float2* __restrict__ T, h16* __restrict__ dqkv, h16* __restrict__ dout,
    h16* __restrict__ dff2, h16* __restrict__ dff1)
{
    int blk = blockIdx.x;
    if (blk < CS_B) {
        int idx = blk * 256 + threadIdx.x;
        if (idx >= CS_N) return;
        int n = idx >> 5, dj = idx & 31;
        float inv = powf(10000.f, -(float)dj * (1.f / 32.f));
        float f = (float)n * inv;
        float sn, cs; sincosf(f, &sn, &cs);
        T[idx] = make_float2(cs, sn);
    } else if (blk < QKV_B) {
        int idx = (blk - CS_B) * 256 + threadIdx.x;
        if (idx >= QKV_N) return;
        int row = idx / (QKVN / 2);
        int p = idx - row * (QKVN / 2);
        int col = p * 2;
        int sect = col >> 10, c = col & 1023;
        const float* rbase = w_qkv + (size_t)row * QKVN;
        float v0, v1;
        if (sect < 2) {
            int h = c >> 6, dj = (c & 63) >> 1;
            v0 = rbase[sect * 1024 + h * 64 + dj];
            v1 = rbase[sect * 1024 + h * 64 + dj + 32];
        } else {
            float2 vv = *(const float2*)(rbase + col);
            v0 = vv.x; v1 = vv.y;
        }
        ((half2*)dqkv)[idx] = __floats2half2_rn(v0, v1);
    } else if (blk < WOUT_B) {
        int i = (blk - QKV_B) * 256 + threadIdx.x;
        if (i >= WOUT_N) return;
        float4 v = ((const float4*)w_out)[i];
        half2* d = (half2*)dout + i * 2;
        d[0] = __floats2half2_rn(v.x, v.y);
        d[1] = __floats2half2_rn(v.z, v.w);
    } else if (blk < WFF2_B) {
        int i = (blk - WOUT_B) * 256 + threadIdx.x;
        if (i >= WFF2_N) return;
        float4 v = ((const float4*)w_ff2)[i];
        half2* d = (half2*)dff2 + i * 2;
        d[0] = __floats2half2_rn(v.x, v.y);
        d[1] = __floats2half2_rn(v.z, v.w);
    } else {
        int idx = (blk - WFF2_B) * 256 + threadIdx.x;
        if (idx >= FF1_N) return;
        int row = idx / (FF1NP / 2);
        int c = idx - row * (FF1NP / 2);
        float a = 0.f, g = 0.f;
        if (c < INNER) {
            const float* rbase = w_ff1 + (size_t)row * FF1N;
            a = rbase[c];
            g = rbase[INNER + c];
        }
        ((half2*)dff1)[(size_t)row * (FF1NP / 2) + c] = __floats2half2_rn(a, g);
    }
}

// ------------------------------- LayerNorm -------------------------------
__global__ __launch_bounds__(256) void ln_kernel(
    const float* __restrict__ X, const float* __restrict__ w,
    const float* __restrict__ b, h16* __restrict__ Y)
{
    __shared__ float sa[8], sb[8];
    int row = blockIdx.x;
    int t = threadIdx.x;
    const float4* xr = (const float4*)(X + (size_t)row * DIMD);
    float4 xv = xr[t];
    float s  = xv.x + xv.y + xv.z + xv.w;
    float sq = xv.x*xv.x + xv.y*xv.y + xv.z*xv.z + xv.w*xv.w;

    int lane = t & 31, wrp = t >> 5;
    #pragma unroll
    for (int o = 16; o; o >>= 1) {
        s  += __shfl_xor_sync(0xffffffffu, s,  o);
        sq += __shfl_xor_sync(0xffffffffu, sq, o);
    }
    if (lane == 0) { sa[wrp] = s; sb[wrp] = sq; }
    __syncthreads();
    if (wrp == 0) {
        s  = (lane < 8) ? sa[lane] : 0.f;
        sq = (lane < 8) ? sb[lane] : 0.f;
        #pragma unroll
        for (int o = 4; o; o >>= 1) {
            s  += __shfl_xor_sync(0xffffffffu, s,  o);
            sq += __shfl_xor_sync(0xffffffffu, sq, o);
        }
        if (lane == 0) { sa[0] = s; sb[0] = sq; }
    }
    __syncthreads();
    float mean = sa[0] * (1.f / DIMD);
    float var  = sb[0] * (1.f / DIMD) - mean * mean;
    float inv  = rsqrtf(var + 1e-5f);

    float4 wv = ((const float4*)w)[t];
    float4 out;
    out.x = (xv.x - mean) * inv * wv.x;
    out.y = (xv.y - mean) * inv * wv.y;
    out.z = (xv.z - mean) * inv * wv.z;
    out.w = (xv.w - mean) * inv * wv.w;
    if (b) {
        float4 bv = ((const float4*)b)[t];
        out.x += bv.x; out.y += bv.y; out.z += bv.z; out.w += bv.w;
    }
    half2* yr = (half2*)(Y + (size_t)row * DIMD);
    yr[2 * t + 0] = __floats2half2_rn(out.x, out.y);
    yr[2 * t + 1] = __floats2half2_rn(out.z, out.w);
}

// --------------------------- tensor-core windowed attention (64q / 4 warps, 2-buf) ---------------------------
// Q fragments hoisted into registers before the tile loop (Q is loop-invariant).
#define AT_STR 72
__global__ __launch_bounds__(128) void attn_mma_kernel(
    const h16* __restrict__ Q, const h16* __restrict__ K,
    const h16* __restrict__ V, h16* __restrict__ O)
{
    __shared__ h16 Qs[64 * AT_STR];
    __shared__ h16 Ks[2][64 * AT_STR];
    __shared__ h16 Vs[2][64 * AT_STR];

    int idx = blockIdx.x;
    int qb = idx & 7;
    int wi = (idx >> 3) & 7;
    int h  = (idx >> 6) & 15;
    int b  = idx >> 10;
    int t  = threadIdx.x;
    int warp = t >> 5, lane = t & 31;
    int g = lane >> 2, q = lane & 3;

    const size_t bh = ((size_t)b * HEADS + h) * NN;
    int n0 = wi * WW + qb * 64;
    int tstart = (wi == 0) ? 8 : 0;
    int tend = qb + 8;

    #pragma unroll
    for (int i = 0; i < 4; i++) {
        int c = t + i * 128;
        int row = c >> 3, cc = c & 7;
        unsigned dst = cvta_s(Qs + row * AT_STR + cc * 8);
        const h16* src = Q + (bh + n0 + row) * DH + cc * 8;
        asm volatile("cp.async.cg.shared.global [%0], [%1], 16;\n" :: "r"(dst), "l"(src));
    }
    asm volatile("cp.async.commit_group;\n" ::: "memory");   // group: Q

    #define KV_ISSUE(tt_, buf_)                                                  \
    {                                                                            \
        int kg = wi * WW - WW + (tt_) * 64;                                      \
        _Pragma("unroll")                                                        \
        for (int i = 0; i < 4; i++) {                                            \
            int c = t + i * 128;                                                 \
            int row = c >> 3, cc = c & 7;                                        \
            const h16* ks_ = K + (bh + kg + row) * DH + cc * 8;                  \
            const h16* vs_ = V + (bh + kg + row) * DH + cc * 8;                  \
            unsigned kd = cvta_s(&Ks[buf_][row * AT_STR + cc * 8]);              \
            unsigned vd = cvta_s(&Vs[buf_][row * AT_STR + cc * 8]);              \
            asm volatile("cp.async.cg.shared.global [%0], [%1], 16;\n" :: "r"(kd), "l"(ks_)); \
            asm volatile("cp.async.cg.shared.global [%0], [%1], 16;\n" :: "r"(vd), "l"(vs_)); \
        }                                                                        \
    }

    KV_ISSUE(tstart, 0);
    asm volatile("cp.async.commit_group;\n" ::: "memory");   // group: KV0
    if (tstart < tend) { KV_ISSUE(tstart + 1, 1); }
    asm volatile("cp.async.commit_group;\n" ::: "memory");   // group: KV1

    // ---- hoist Q fragments to registers (loop-invariant) ----
    unsigned aq[4][4];
    {
        asm volatile("cp.async.wait_group 2;\n" ::: "memory");   // Q arrived
        __syncthreads();
        #pragma unroll
        for (int ks = 0; ks < 4; ks++)
            ldsm4(aq[ks], cvta_s(Qs + (warp * 16 + (lane & 15)) * AT_STR
                                 + ks * 16 + ((lane >> 4) << 3)));
    }

    float o_[8][4];
    #pragma unroll
    for (int i = 0; i < 8; i++)
        #pragma unroll
        for (int j = 0; j < 4; j++) o_[i][j] = 0.f;
    float m0 = -1e30f, m1 = -1e30f, l0 = 0.f, l1 = 0.f;

    int bsel = 0;
    for (int tt = tstart; tt <= tend; tt++) {
        asm volatile("cp.async.wait_group 1;\n" ::: "memory");
        __syncthreads();

        float sc[8][4];
        #pragma unroll
        for (int i = 0; i < 8; i++)
            #pragma unroll
            for (int j = 0; j < 4; j++) sc[i][j] = 0.f;

        #pragma unroll
        for (int ks = 0; ks < 4; ks++) {
            #pragma unroll
            for (int nb = 0; nb < 4; nb++) {
                unsigned bk[4];
                int krow = nb * 16 + (lane & 7) + ((lane >> 4) << 3);
                int kcol = ks * 16 + (((lane >> 3) & 1) << 3);
                ldsm4(bk, cvta_s(&Ks[bsel][krow * AT_STR + kcol]));
                mma16816(sc[nb * 2],     aq[ks], bk[0], bk[1]);
                mma16816(sc[nb * 2 + 1], aq[ks], bk[2], bk[3]);
            }
        }

        if (tt == tend) {
            int r0 = warp * 16 + g, r1 = r0 + 8;
            #pragma unroll
            for (int nf = 0; nf < 8; nf++) {
                int c0 = nf * 8 + q * 2;
                if (c0     > r0) sc[nf][0] = -1e30f;
                if (c0 + 1 > r0) sc[nf][1] = -1e30f;
                if (c0     > r1) sc[nf][2] = -1e30f;
                if (c0 + 1 > r1) sc[nf][3] = -1e30f;
            }
        }

        float mt0 = -1e30f, mt1 = -1e30f;
        #pragma unroll
        for (int nf = 0; nf < 8; nf++) {
            mt0 = fmaxf(mt0, fmaxf(sc[nf][0], sc[nf][1]));
            mt1 = fmaxf(mt1, fmaxf(sc[nf][2], sc[nf][3]));
        }
        mt0 = fmaxf(mt0, __shfl_xor_sync(0xffffffffu, mt0, 1));
        mt0 = fmaxf(mt0, __shfl_xor_sync(0xffffffffu, mt0, 2));
        mt1 = fmaxf(mt1, __shfl_xor_sync(0xffffffffu, mt1, 1));
        mt1 = fmaxf(mt1, __shfl_xor_sync(0xffffffffu, mt1, 2));
        float mn0 = fmaxf(m0, mt0), mn1 = fmaxf(m1, mt1);
        float cor0 = ex2f(m0 - mn0), cor1 = ex2f(m1 - mn1);
        m0 = mn0; m1 = mn1;
        float s0 = 0.f, s1 = 0.f;
        #pragma unroll
        for (int nf = 0; nf < 8; nf++) {
            sc[nf][0] = ex2f(sc[nf][0] - mn0);
            sc[nf][1] = ex2f(sc[nf][1] - mn0);
            sc[nf][2] = ex2f(sc[nf][2] - mn1);
            sc[nf][3] = ex2f(sc[nf][3] - mn1);
            s0 += sc[nf][0] + sc[nf][1];
            s1 += sc[nf][2] + sc[nf][3];
        }
        l0 = l0 * cor0 + s0;
        l1 = l1 * cor1 + s1;
        #pragma unroll
        for (int nf = 0; nf < 8; nf++) {
            o_[nf][0] *= cor0; o_[nf][1] *= cor0;
            o_[nf][2] *= cor1; o_[nf][3] *= cor1;
        }

        #pragma unroll
        for (int ks = 0; ks < 4; ks++) {
            unsigned ap[4];
            ap[0] = packh2(sc[2 * ks][0],     sc[2 * ks][1]);
            ap[1] = packh2(sc[2 * ks][2],     sc[2 * ks][3]);
            ap[2] = packh2(sc[2 * ks + 1][0], sc[2 * ks + 1][1]);
            ap[3] = packh2(sc[2 * ks + 1][2], sc[2 * ks + 1][3]);
            #pragma unroll
            for (int nb = 0; nb < 4; nb++) {
                unsigned bv[4];
                ldsm4t(bv, cvta_s(&Vs[bsel][(ks * 16 + (lane & 15)) * AT_STR
                                            + nb * 16 + ((lane >> 4) << 3)]));
                mma16816(o_[nb * 2],     ap, bv[0], bv[1]);
                mma16816(o_[nb * 2 + 1], ap, bv[2], bv[3]);
            }
        }

        __syncthreads();
        if (tt + 2 <= tend) { KV_ISSUE(tt + 2, bsel); }
        asm volatile("cp.async.commit_group;\n" ::: "memory");
        bsel ^= 1;
    }

    l0 += __shfl_xor_sync(0xffffffffu, l0, 1);
    l0 += __shfl_xor_sync(0xffffffffu, l0, 2);
    l1 += __shfl_xor_sync(0xffffffffu, l1, 1);
    l1 += __shfl_xor_sync(0xffffffffu, l1, 2);
    float li0 = 1.f / l0, li1 = 1.f / l1;

    int row0 = n0 + warp * 16 + g;
    h16* p0 = O + ((size_t)(b * NN + row0)) * DIMD + h * DH;
    h16* p1 = O + ((size_t)(b * NN + row0 + 8)) * DIMD + h * DH;
    #pragma unroll
    for (int nf = 0; nf < 8; nf++) {
        *(half2*)(p0 + nf * 8 + q * 2) = __floats2half2_rn(o_[nf][0] * li0, o_[nf][1] * li0);
        *(half2*)(p1 + nf * 8 + q * 2) = __floats2half2_rn(o_[nf][2] * li1, o_[nf][3] * li1);
    }
    #undef KV_ISSUE
}

// ------------------------------ FP16 tensor-core GEMM (128x128, k64 x 3-stage) ------------------------------
// OUTMODE: 0 = fp32 out, 1 = fp16 out, 2 = fused GEGLU,
//          3 = fused rope + q/k/v head split
#define STAGES 3
#define ASTR 72
#define BSTR 136
#define A_STAGE (128*ASTR)
#define B_STAGE (64*BSTR)
#define GEMM_SMEM (STAGES*(A_STAGE+B_STAGE)*2)

template<bool RES, int OUTMODE>
__global__ __launch_bounds__(256) void h16_gemm(
    const h16* __restrict__ A, int lda,
    const h16* __restrict__ B, int ldb,
    const float* __restrict__ R, void* __restrict__ Cv,
    int Nc, int Kb, int Kpad,
    const float2* __restrict__ CS = nullptr,
    h16* __restrict__ Qo = nullptr, h16* __restrict__ Ko = nullptr,
    h16* __restrict__ Vo = nullptr)
{
    extern __shared__ char smem_raw[];
    h16* As = (h16*)smem_raw;
    h16* Bs = (h16*)(smem_raw + (size_t)STAGES * A_STAGE * 2);

    const int t = threadIdx.x;
    const int rowBase = blockIdx.y * 128, colBase = blockIdx.x * 128;
    const int warp = t >> 5, lane = t & 31;
    const int wm = warp >> 2, wn = warp & 3;
    const int q = lane & 3, g = lane >> 2;

    float acc[4][4][4];
    #pragma unroll
    for (int i = 0; i < 4; i++)
        #pragma unroll
        for (int j = 0; j < 4; j++)
            #pragma unroll
            for (int rr = 0; rr < 4; rr++) acc[i][j][rr] = 0.f;

    #define ISSUE(k0, s)                                                        \
    {                                                                           \
        _Pragma("unroll")                                                       \
        for (int i = 0; i < 4; i++) {                                           \
            int c = t + i * 256;                                                \
            int row = c >> 3, cc = c & 7;                                       \
            const h16* src = A + (size_t)(rowBase + row) * lda + (k0) + cc * 8; \
            unsigned dst = cvta_s(As + (s) * A_STAGE + row * ASTR + cc * 8);    \
            asm volatile("cp.async.cg.shared.global [%0], [%1], 16;\n"          \
                         :: "r"(dst), "l"(src));                                \
        }                                                                       \
        _Pragma("unroll")                                                       \
        for (int i = 0; i < 4; i++) {                                           \
            int c = t + i * 256;                                                \
            int row = c >> 4, cc = c & 15;                                      \
            int kidx = (k0) + row;                                              \
            int bytes = (kidx < Kb) ? 16 : 0;                                   \
            const h16* src = B + (size_t)(kidx < Kb ? kidx : 0) * ldb           \
                               + colBase + cc * 8;                              \
            unsigned dst = cvta_s(Bs + (s) * B_STAGE + row * BSTR + cc * 8);    \
            asm volatile("cp.async.cg.shared.global [%0], [%1], 16, %2;\n"      \
                         :: "r"(dst), "l"(src), "r"(bytes));                    \
        }                                                                       \
    }

    #define COMPUTE(s)                                                          \
    {                                                                           \
        _Pragma("unroll")                                                       \
        for (int ks = 0; ks < 64; ks += 16) {                                   \
            unsigned a[4][4], bfr[2][4];                                        \
            _Pragma("unroll")                                                   \
            for (int mf = 0; mf < 4; mf++) {                                    \
                int mrow = wm * 64 + mf * 16 + (lane & 15);                     \
                int colofs = ks + ((lane >> 4) << 3);                           \
                ldsm4(a[mf], cvta_s(As + (s) * A_STAGE + mrow * ASTR + colofs));\
            }                                                                   \
            _Pragma("unroll")                                                   \
            for (int nh = 0; nh < 2; nh++) {                                    \
                int krow = ks + (lane & 15);                                    \
                int col = wn * 32 + nh * 16 + ((lane >> 4) << 3);               \
                ldsm4t(bfr[nh], cvta_s(Bs + (s) * B_STAGE + krow * BSTR + col));\
            }                                                                   \
            _Pragma("unroll")                                                   \
            for (int mf = 0; mf < 4; mf++)                                      \
                _Pragma("unroll")                                               \
                for (int nf = 0; nf < 4; nf++)                                  \
                    mma16816(acc[mf][nf], a[mf],                                \
                             bfr[nf >> 1][(nf & 1) * 2 + 0],                    \
                             bfr[nf >> 1][(nf & 1) * 2 + 1]);                   \
        }                                                                       \
    }

    const int nstage = Kpad / 64;
    ISSUE(0, 0);
    asm volatile("cp.async.commit_group;\n" ::: "memory");
    ISSUE(64, 1);
    asm volatile("cp.async.commit_group;\n" ::: "memory");

    for (int it = 0; it < nstage; it++) {
        asm volatile("cp.async.wait_group 1;\n" ::: "memory");
        __syncthreads();
        int s = it % 3;
        COMPUTE(s);
        if (it + 2 < nstage) {
            int k0 = (it + 2) * 64;
            int s2 = (it + 2) % 3;
            ISSUE(k0, s2);
        }
        asm volatile("cp.async.commit_group;\n" ::: "memory");
    }

    #pragma unroll
    for (int mf = 0; mf < 4; mf++) {
        #pragma unroll
        for (int i = 0; i < 2; i++) {
            int grow = rowBase + wm * 64 + mf * 16 + g + i * 8;
            #pragma unroll
            for (int nf = 0; nf < 4; nf++) {
                int gcol = colBase + wn * 32 + nf * 8 + q * 2;
                if (gcol < Nc) {
                    float v0 = acc[mf][nf][i * 2 + 0];
                    float v1 = acc[mf][nf][i * 2 + 1];
                    if (RES) {
                        const float* Rp = R + (size_t)grow * Nc + gcol;
                        v0 += Rp[0]; v1 += Rp[1];
                    }
                    if (OUTMODE == 0) {
                        float* Cf = (float*)Cv;
                        *(float2*)(Cf + (size_t)grow * Nc + gcol) = make_float2(v0, v1);
                    } else if (OUTMODE == 1) {
                        h16* Ch = (h16*)Cv;
                        *(half2*)(Ch + (size_t)grow * Nc + gcol) = __floats2half2_rn(v0, v1);
                    } else if (OUTMODE == 2) {
                        float ge = 0.5f * v1 * (1.f + erff(v1 * 0.70710678118654752f));
                        h16* Ch = (h16*)Cv;
                        Ch[(size_t)grow * (Nc / 2) + (gcol >> 1)] = __float2half_rn(v0 * ge);
                    } else {
                        int sect = gcol >> 10, c = gcol & 1023;
                        int hh = c >> 6, r = c & 63;
                        int bb2 = grow >> 12, n = grow & (NN - 1);
                        size_t o = ((size_t)(bb2 * HEADS + hh) * NN + n) * DH + r;
                        if (sect == 2) {
                            *(half2*)(Vo + o) = __floats2half2_rn(v0, v1);
                        } else {
                            int dj = r >> 1;
                            float2 cs = CS[n * 32 + dj];
                            float y0 = v0 * cs.x - v1 * cs.y;
                            float y1 = v1 * cs.x + v0 * cs.y;
                            if (sect == 0) { y0 *= QSCALE; y1 *= QSCALE; }
                            h16* P = (sect == 0) ? Qo : Ko;
                            *(half2*)(P + o) = __floats2half2_rn(y0, y1);
                        }
                    }
                }
            }
        }
    }
    #undef ISSUE
    #undef COMPUTE
}

// ------------------------------ launch ------------------------------
extern "C" void kernel_launch(void* const* d_in, const int* in_sizes, int n_in,
                              void* d_out, int out_size)
{
    const float* x     = (const float*)d_in[0];
    const float* ln1_w = (const float*)d_in[1];
    const float* ln1_b = (const float*)d_in[2];
    const float* w_qkv = (const float*)d_in[3];
    const float* w_out = (const float*)d_in[4];
    const float* ln2_w = (const float*)d_in[5];
    const float* w_ff1 = (const float*)d_in[6];
    const float* w_ff2 = (const float*)d_in[7];
    float* out = (float*)d_out;

    h16 *p_hh, *p_qh, *p_kh, *p_vh, *p_attnh, *p_ggh;
    h16 *p_wqkv, *p_wout, *p_wff1, *p_wff2;
    float *p_x1;
    float2 *p_cs;
    cudaGetSymbolAddress((void**)&p_hh,    g_hh);
    cudaGetSymbolAddress((void**)&p_qh,    g_qh);
    cudaGetSymbolAddress((void**)&p_kh,    g_kh);
    cudaGetSymbolAddress((void**)&p_vh,    g_vh);
    cudaGetSymbolAddress((void**)&p_attnh, g_attnh);
    cudaGetSymbolAddress((void**)&p_x1,    g_x1);
    cudaGetSymbolAddress((void**)&p_ggh,   g_ggh);
    cudaGetSymbolAddress((void**)&p_cs,    g_cs);
    cudaGetSymbolAddress((void**)&p_wqkv,  g_wqkv);
    cudaGetSymbolAddress((void**)&p_wout,  g_wout);
    cudaGetSymbolAddress((void**)&p_wff1,  g_wff1);
    cudaGetSymbolAddress((void**)&p_wff2,  g_wff2);

    cudaFuncSetAttribute(h16_gemm<false,2>, cudaFuncAttributeMaxDynamicSharedMemorySize, GEMM_SMEM);
    cudaFuncSetAttribute(h16_gemm<false,3>, cudaFuncAttributeMaxDynamicSharedMemorySize, GEMM_SMEM);
    cudaFuncSetAttribute(h16_gemm<true,0>,  cudaFuncAttributeMaxDynamicSharedMemorySize, GEMM_SMEM);

    // 0. merged tables + weight converts
    prep_kernel<<<FF1_B, 256>>>(w_qkv, w_out, w_ff2, w_ff1,
                                p_cs, p_wqkv, p_wout, p_wff2, p_wff1);

    // 1. LN1 -> fp16
    ln_kernel<<<ROWS, 256>>>(x, ln1_w, ln1_b, p_hh);
    // 2. QKV GEMM + fused rope + head split (M=8192, N=3072, K=1024)
    h16_gemm<false,3><<<dim3(QKVN / 128, ROWS / 128), 256, GEMM_SMEM>>>(
        p_hh, DIMD, p_wqkv, QKVN, nullptr, nullptr, QKVN, DIMD, DIMD,
        p_cs, p_qh, p_kh, p_vh);
    // 3. tensor-core windowed attention (64q / 4 warps, hoisted Q fragments)
    attn_mma_kernel<<<BB * HEADS * NW * (WW / 64), 128>>>(p_qh, p_kh, p_vh, p_attnh);
    // 4. out proj + residual (M=8192, N=1024, K=1024) -> fp32
    h16_gemm<true,0><<<dim3(DIMD / 128, ROWS / 128), 256, GEMM_SMEM>>>(
        p_attnh, DIMD, p_wout, DIMD, x, p_x1, DIMD, DIMD, DIMD);
    // 5. LN2 -> fp16
    ln_kernel<<<ROWS, 256>>>(p_x1, ln2_w, nullptr, p_hh);
    // 6. FF1 + fused GEGLU (M=8192, Nc=5504 interleaved, K=1024) -> gg fp16 [8192 x 2752]
    h16_gemm<false,2><<<dim3(FF1NP / 128, ROWS / 128), 256, GEMM_SMEM>>>(
        p_hh, DIMD, p_wff1, FF1NP, nullptr, p_ggh, FF1NP, DIMD, DIMD);
    // 7. FF2 + residual -> out (M=8192, N=1024, K=2752 incl. exact zero pad)
    h16_gemm<true,0><<<dim3(DIMD / 128, ROWS / 128), 256, GEMM_SMEM>>>(
        p_ggh, GGW2, p_wff2, DIMD, p_x1, out, DIMD, INNER, GGW2);
}